// round 9
// baseline (speedup 1.0000x reference)
#include <cuda_runtime.h>
#include <cuda_bf16.h>
#include <math.h>
#include <stdint.h>

// Problem constants
#define BATCH 8
#define T_SEQ 1024
#define C_EMB 768
#define NH    8
#define HD    96
#define M_ROWS (BATCH * T_SEQ)   // 8192
#define GK    768

// ---------------------------------------------------------------------------
// Scratch: pre-split bf16 hi/lo arrays
// ---------------------------------------------------------------------------
__device__ __nv_bfloat16 g_xh[(size_t)M_ROWS * C_EMB];
__device__ __nv_bfloat16 g_xl[(size_t)M_ROWS * C_EMB];
__device__ __nv_bfloat16 g_w1h[(size_t)3 * C_EMB * C_EMB];
__device__ __nv_bfloat16 g_w1l[(size_t)3 * C_EMB * C_EMB];
__device__ __nv_bfloat16 g_w2h[(size_t)C_EMB * C_EMB];
__device__ __nv_bfloat16 g_w2l[(size_t)C_EMB * C_EMB];
__device__ __nv_bfloat16 g_qkvh[(size_t)M_ROWS * 3 * C_EMB];
__device__ __nv_bfloat16 g_qkvl[(size_t)M_ROWS * 3 * C_EMB];
__device__ __nv_bfloat16 g_atth[(size_t)M_ROWS * C_EMB];
__device__ __nv_bfloat16 g_attl[(size_t)M_ROWS * C_EMB];

// ---------------------------------------------------------------------------
// PTX helpers (baseline ISA at compute_103)
// ---------------------------------------------------------------------------
__device__ __forceinline__ uint32_t smem_u32(const void* p) {
    uint32_t a;
    asm("{ .reg .u64 t; cvta.to.shared.u64 t, %1; cvt.u32.u64 %0, t; }"
        : "=r"(a) : "l"(p));
    return a;
}
__device__ __forceinline__ void mma_bf16(
    float& c0, float& c1, float& c2, float& c3,
    uint32_t a0, uint32_t a1, uint32_t a2, uint32_t a3,
    uint32_t b0, uint32_t b1)
{
    asm volatile(
        "mma.sync.aligned.m16n8k16.row.col.f32.bf16.bf16.f32 "
        "{%0,%1,%2,%3}, {%4,%5,%6,%7}, {%8,%9}, {%0,%1,%2,%3};"
        : "+f"(c0), "+f"(c1), "+f"(c2), "+f"(c3)
        : "r"(a0), "r"(a1), "r"(a2), "r"(a3), "r"(b0), "r"(b1));
}
__device__ __forceinline__ void ldm_x4(
    uint32_t& r0, uint32_t& r1, uint32_t& r2, uint32_t& r3, uint32_t saddr)
{
    asm volatile("ldmatrix.sync.aligned.m8n8.x4.shared.b16 {%0,%1,%2,%3}, [%4];"
        : "=r"(r0), "=r"(r1), "=r"(r2), "=r"(r3) : "r"(saddr));
}
__device__ __forceinline__ void ldm_x4_t(
    uint32_t& r0, uint32_t& r1, uint32_t& r2, uint32_t& r3, uint32_t saddr)
{
    asm volatile("ldmatrix.sync.aligned.m8n8.x4.trans.shared.b16 {%0,%1,%2,%3}, [%4];"
        : "=r"(r0), "=r"(r1), "=r"(r2), "=r"(r3) : "r"(saddr));
}
__device__ __forceinline__ void cp16(uint32_t dst, const void* src) {
    asm volatile("cp.async.cg.shared.global [%0], [%1], 16;"
        :: "r"(dst), "l"(src) : "memory");
}
#define CP_COMMIT() asm volatile("cp.async.commit_group;" ::: "memory")
#define CP_WAIT0()  asm volatile("cp.async.wait_group 0;" ::: "memory")
#define CP_WAIT1()  asm volatile("cp.async.wait_group 1;" ::: "memory")

__device__ __forceinline__ uint32_t pkbf(__nv_bfloat16 a, __nv_bfloat16 b) {
    __nv_bfloat162 t(a, b);
    return *reinterpret_cast<uint32_t*>(&t);
}
__device__ __forceinline__ uint32_t pkf2(float a, float b) {
    __nv_bfloat162 t = __float22bfloat162_rn(make_float2(a, b));
    return *reinterpret_cast<uint32_t*>(&t);
}
__device__ __forceinline__ uint32_t pksplit(float a, float b, uint32_t& lo) {
    __nv_bfloat16 ha = __float2bfloat16_rn(a);
    __nv_bfloat16 hb = __float2bfloat16_rn(b);
    lo = pkf2(a - __bfloat162float(ha), b - __bfloat162float(hb));
    return pkbf(ha, hb);
}

// ---------------------------------------------------------------------------
// Pre-split fp32 -> bf16 hi/lo (elementwise)
// ---------------------------------------------------------------------------
__global__ void split_f32(const float* __restrict__ s,
                          __nv_bfloat16* __restrict__ h,
                          __nv_bfloat16* __restrict__ l, int n4)
{
    int i = blockIdx.x * blockDim.x + threadIdx.x;
    int stride = gridDim.x * blockDim.x;
    for (; i < n4; i += stride) {
        float4 v = ((const float4*)s)[i];
        uint32_t l0, l1;
        uint32_t h0 = pksplit(v.x, v.y, l0);
        uint32_t h1 = pksplit(v.z, v.w, l1);
        ((uint2*)h)[i] = make_uint2(h0, h1);
        ((uint2*)l)[i] = make_uint2(l0, l1);
    }
}

// ---------------------------------------------------------------------------
// Split-bf16 GEMM, swizzled pad-free smem, cp.async double-buffered.
//   C = A * W^T + bias;  D = Ah*Bh + Ah*Bl + Al*Bh
// CTA 64x128 (128 thr, 4 warps each 64x32), K chunked 32; 4 CTAs/SM.
// Smem layout per stage (24576 B): Ah@0 (4 KB), Al@4096, Bh@8192 (8 KB),
// Bl@16384. Row = 64 B (32 bf16); 16B unit at column c ^ ((r>>1)&3).
// ---------------------------------------------------------------------------
#define STAGE_B 24576
#define GEMM_SMEM_BYTES (2 * STAGE_B)   // 49152
#define NCHUNK (GK / 32)

template <bool SPLIT_OUT>
__global__ __launch_bounds__(128, 4) void gemm_mma(
    const __nv_bfloat16* __restrict__ Ahg, const __nv_bfloat16* __restrict__ Alg,
    const __nv_bfloat16* __restrict__ Bhg, const __nv_bfloat16* __restrict__ Blg,
    const float* __restrict__ bias,
    float* __restrict__ Cf,
    __nv_bfloat16* __restrict__ Ch, __nv_bfloat16* __restrict__ Cl,
    int N)
{
    extern __shared__ char smc[];

    const int tid  = threadIdx.x;
    const int w    = tid >> 5;
    const int lane = tid & 31;
    const int gr   = lane >> 2;
    const int lc   = lane & 3;
    const int bm   = blockIdx.y * 64;
    const int bn   = blockIdx.x * 128;

    const uint32_t smbase = smem_u32(smc);

    // cp.async loader: r = ar (+32j), 16B chunk ck; swizzle (ar>>1)&3 (const per thread)
    const int ar = tid >> 2, ack = tid & 3;
    const uint32_t lsw = (uint32_t)(((ar >> 1) & 3) ^ ack) * 16;

    auto issue_chunk = [&](int t, int buf) {
        const uint32_t bb = smbase + (uint32_t)(buf * STAGE_B);
        const int k0 = t * 32;
#pragma unroll
        for (int j = 0; j < 2; j++) {
            int r = ar + 32 * j;
            const size_t so = (size_t)(bm + r) * GK + k0 + ack * 8;
            uint32_t d = bb + (uint32_t)(r * 64) + lsw;
            cp16(d, Ahg + so);
            cp16(d + 4096, Alg + so);
        }
#pragma unroll
        for (int j = 0; j < 4; j++) {
            int r = ar + 32 * j;
            const size_t so = (size_t)(bn + r) * GK + k0 + ack * 8;
            uint32_t d = bb + 8192u + (uint32_t)(r * 64) + lsw;
            cp16(d, Bhg + so);
            cp16(d + 8192, Blg + so);
        }
        CP_COMMIT();
    };

    // ldmatrix per-lane components
    const int hl  = lane >> 4;                 // 0/1
    const int rl  = lane & 15;                 // A row within 16
    const int swA = (rl >> 1) & 3;
    const int l7  = lane & 7;
    const int rBl = (hl << 3) + l7;            // B row within 16
    const int swB = (l7 >> 1) & 3;
    const int cB0 = (lane >> 3) & 1;
    const uint32_t aRow = (uint32_t)(rl * 64);
    const uint32_t bRow = (uint32_t)((w * 32 + rBl) * 64);

    float acc[4][4][4];
#pragma unroll
    for (int mt = 0; mt < 4; mt++)
#pragma unroll
        for (int nt = 0; nt < 4; nt++)
#pragma unroll
            for (int r = 0; r < 4; r++) acc[mt][nt][r] = 0.f;

    issue_chunk(0, 0);
    issue_chunk(1, 1);

    for (int t = 0; t < NCHUNK; t++) {
        if (t + 1 < NCHUNK) { CP_WAIT1(); } else { CP_WAIT0(); }
        __syncthreads();

        {
            const uint32_t bufb = smbase + (uint32_t)((t & 1) * STAGE_B);
            const uint32_t ah_b = bufb + aRow;
            const uint32_t bh_b = bufb + 8192u + bRow;

#pragma unroll
            for (int ks = 0; ks < 2; ks++) {
                const uint32_t colA = (uint32_t)(((ks * 2 + hl) ^ swA) * 16);
                const uint32_t colB = (uint32_t)(((ks * 2 + cB0) ^ swB) * 16);
                uint32_t af[4][4], bhf[4][2], blf[4][2];
#pragma unroll
                for (int mt = 0; mt < 4; mt++)
                    ldm_x4(af[mt][0], af[mt][1], af[mt][2], af[mt][3],
                           ah_b + (uint32_t)(mt * 1024) + colA);
#pragma unroll
                for (int p = 0; p < 2; p++) {
                    const uint32_t off = (uint32_t)(p * 1024) + colB;
                    ldm_x4(bhf[2 * p][0], bhf[2 * p][1], bhf[2 * p + 1][0], bhf[2 * p + 1][1],
                           bh_b + off);
                    ldm_x4(blf[2 * p][0], blf[2 * p][1], blf[2 * p + 1][0], blf[2 * p + 1][1],
                           bh_b + 8192u + off);
                }
#pragma unroll
                for (int mt = 0; mt < 4; mt++)
#pragma unroll
                    for (int nt = 0; nt < 4; nt++) {
                        mma_bf16(acc[mt][nt][0], acc[mt][nt][1],
                                 acc[mt][nt][2], acc[mt][nt][3],
                                 af[mt][0], af[mt][1], af[mt][2], af[mt][3],
                                 bhf[nt][0], bhf[nt][1]);
                        mma_bf16(acc[mt][nt][0], acc[mt][nt][1],
                                 acc[mt][nt][2], acc[mt][nt][3],
                                 af[mt][0], af[mt][1], af[mt][2], af[mt][3],
                                 blf[nt][0], blf[nt][1]);
                    }
#pragma unroll
                for (int mt = 0; mt < 4; mt++)
                    ldm_x4(af[mt][0], af[mt][1], af[mt][2], af[mt][3],
                           ah_b + 4096u + (uint32_t)(mt * 1024) + colA);
#pragma unroll
                for (int mt = 0; mt < 4; mt++)
#pragma unroll
                    for (int nt = 0; nt < 4; nt++)
                        mma_bf16(acc[mt][nt][0], acc[mt][nt][1],
                                 acc[mt][nt][2], acc[mt][nt][3],
                                 af[mt][0], af[mt][1], af[mt][2], af[mt][3],
                                 bhf[nt][0], bhf[nt][1]);
            }
        }
        __syncthreads();
        if (t + 2 < NCHUNK) issue_chunk(t + 2, t & 1);
    }

    // epilogue
#pragma unroll
    for (int nt = 0; nt < 4; nt++) {
        const int col = bn + w * 32 + nt * 8 + lc * 2;
        const float2 bj = *(const float2*)(bias + col);
#pragma unroll
        for (int mt = 0; mt < 4; mt++) {
            const int row0 = bm + mt * 16 + gr;
            float x0 = acc[mt][nt][0] + bj.x, y0 = acc[mt][nt][1] + bj.y;
            float x1 = acc[mt][nt][2] + bj.x, y1 = acc[mt][nt][3] + bj.y;
            if (SPLIT_OUT) {
                uint32_t lo0, lo1;
                uint32_t hi0 = pksplit(x0, y0, lo0);
                uint32_t hi1 = pksplit(x1, y1, lo1);
                *(uint32_t*)(Ch + (size_t)row0 * N + col) = hi0;
                *(uint32_t*)(Cl + (size_t)row0 * N + col) = lo0;
                *(uint32_t*)(Ch + (size_t)(row0 + 8) * N + col) = hi1;
                *(uint32_t*)(Cl + (size_t)(row0 + 8) * N + col) = lo1;
            } else {
                *(float2*)(Cf + (size_t)row0 * N + col) = make_float2(x0, y0);
                *(float2*)(Cf + (size_t)(row0 + 8) * N + col) = make_float2(x1, y1);
            }
        }
    }
}

// ---------------------------------------------------------------------------
// Flash attention (unchanged from R8): BQ=128, 256 thr, cp.async pipelined,
// split-bf16 both phases, V row-major + ldmatrix.trans.
// ---------------------------------------------------------------------------
#define FKST 104
#define FBUF_B (64 * FKST * 2)
#define FBUF_TOTAL (4 * FBUF_B)
#define FL_SMEM_BYTES (2 * FBUF_TOTAL)

__global__ __launch_bounds__(256, 1) void flash_mma(
    const __nv_bfloat16* __restrict__ qkvh,
    const __nv_bfloat16* __restrict__ qkvl,
    __nv_bfloat16* __restrict__ atth,
    __nv_bfloat16* __restrict__ attl)
{
    extern __shared__ char fsm[];
    const uint32_t smbase = smem_u32(fsm);

    const int qtp = 7 - (int)blockIdx.x;
    const int h   = blockIdx.y;
    const int b   = blockIdx.z;
    const int tid  = threadIdx.x;
    const int w    = tid >> 5;
    const int lane = tid & 31;
    const int gr   = lane >> 2;
    const int lc   = lane & 3;
    const int r0l  = w * 16 + gr;
    const int r1l  = r0l + 8;

    const int nkt = 2 * qtp + 2;
    const float rscale = 0.10206207261596577f;

    auto issue_tile = [&](int kt, int buf) {
        const uint32_t bb = smbase + (uint32_t)(buf * FBUF_TOTAL);
        const size_t rowbase = (size_t)(b * T_SEQ + kt * 64);
        const size_t koff = (size_t)C_EMB + h * HD;
        const size_t voff = (size_t)2 * C_EMB + h * HD;
#pragma unroll
        for (int j = 0; j < 3; j++) {
            int i = tid + 256 * j;
            int r = i / 12, ck = i % 12;
            const size_t so = (rowbase + r) * (3 * C_EMB) + ck * 8;
            uint32_t d = bb + (uint32_t)(r * 208 + ck * 16);
            cp16(d, qkvh + so + koff);
            cp16(d + FBUF_B, qkvl + so + koff);
            cp16(d + 2 * FBUF_B, qkvh + so + voff);
            cp16(d + 3 * FBUF_B, qkvl + so + voff);
        }
        CP_COMMIT();
    };

    issue_tile(0, 0);

    {
        const uint32_t qb = smbase + FBUF_TOTAL;
        const size_t rowbase = (size_t)(b * T_SEQ + qtp * 128);
        const size_t qoff = (size_t)h * HD;
#pragma unroll
        for (int j = 0; j < 6; j++) {
            int i = tid + 256 * j;
            int r = i / 12, ck = i % 12;
            const size_t so = (rowbase + r) * (3 * C_EMB) + qoff + ck * 8;
            uint32_t d = qb + (uint32_t)(r * 208 + ck * 16);
            *(uint4*)(fsm + (d - smbase)) = *(const uint4*)(qkvh + so);
            *(uint4*)(fsm + (d - smbase) + 26624) = *(const uint4*)(qkvl + so);
        }
    }
    __syncthreads();

    uint32_t Qhf[6][4], Qlf[6][4];
    {
        const uint32_t afl = (uint32_t)((lane & 15) * 208 + ((lane >> 4) << 4));
        const uint32_t qh_b = smbase + FBUF_TOTAL + (uint32_t)(w * 16 * 208) + afl;
#pragma unroll
        for (int ks = 0; ks < 6; ks++) {
            ldm_x4(Qhf[ks][0], Qhf[ks][1], Qhf[ks][2], Qhf[ks][3], qh_b + ks * 32);
            ldm_x4(Qlf[ks][0], Qlf[ks][1], Qlf[ks][2], Qlf[ks][3], qh_b + 26624 + ks * 32);
        }
    }
    __syncthreads();
    issue_tile(1, 1);

    const uint32_t kfl = (uint32_t)((((lane >> 4) << 3) + (lane & 7)) * 208
                                    + ((lane >> 3) & 1) * 16);
    const uint32_t vfl = (uint32_t)((lane & 15) * 208 + ((lane >> 4) << 4));

    float accO[12][4];
#pragma unroll
    for (int nt = 0; nt < 12; nt++)
#pragma unroll
        for (int r = 0; r < 4; r++) accO[nt][r] = 0.f;
    float m0 = -1e30f, m1 = -1e30f, l0 = 0.f, l1 = 0.f;

    for (int kt = 0; kt < nkt; kt++) {
        if (kt + 1 < nkt) { CP_WAIT1(); } else { CP_WAIT0(); }
        __syncthreads();

        const uint32_t bb = smbase + (uint32_t)((kt & 1) * FBUF_TOTAL);
        const uint32_t kh_b = bb + kfl;
        const uint32_t kl_b = kh_b + FBUF_B;
        const uint32_t vh_b = bb + 2 * FBUF_B + vfl;
        const uint32_t vl_b = vh_b + FBUF_B;

        float accS[8][4];
#pragma unroll
        for (int nt = 0; nt < 8; nt++)
#pragma unroll
            for (int r = 0; r < 4; r++) accS[nt][r] = 0.f;

#pragma unroll
        for (int ks = 0; ks < 6; ks++) {
            const uint32_t kxb = (uint32_t)(ks * 32);
            uint32_t bh[8][2], bl[8][2];
#pragma unroll
            for (int p = 0; p < 4; p++) {
                uint32_t off = (uint32_t)(p * 16 * 208) + kxb;
                ldm_x4(bh[2 * p][0], bh[2 * p][1], bh[2 * p + 1][0], bh[2 * p + 1][1],
                       kh_b + off);
                ldm_x4(bl[2 * p][0], bl[2 * p][1], bl[2 * p + 1][0], bl[2 * p + 1][1],
                       kl_b + off);
            }
#pragma unroll
            for (int nt = 0; nt < 8; nt++) {
                mma_bf16(accS[nt][0], accS[nt][1], accS[nt][2], accS[nt][3],
                         Qhf[ks][0], Qhf[ks][1], Qhf[ks][2], Qhf[ks][3],
                         bh[nt][0], bh[nt][1]);
                mma_bf16(accS[nt][0], accS[nt][1], accS[nt][2], accS[nt][3],
                         Qhf[ks][0], Qhf[ks][1], Qhf[ks][2], Qhf[ks][3],
                         bl[nt][0], bl[nt][1]);
                mma_bf16(accS[nt][0], accS[nt][1], accS[nt][2], accS[nt][3],
                         Qlf[ks][0], Qlf[ks][1], Qlf[ks][2], Qlf[ks][3],
                         bh[nt][0], bh[nt][1]);
            }
        }

#pragma unroll
        for (int nt = 0; nt < 8; nt++)
#pragma unroll
            for (int r = 0; r < 4; r++) accS[nt][r] *= rscale;

        if (kt >= 2 * qtp) {
            const int qg0 = qtp * 128 + r0l;
            const int qg1 = qg0 + 8;
#pragma unroll
            for (int nt = 0; nt < 8; nt++) {
                int c0 = kt * 64 + nt * 8 + 2 * lc, c1 = c0 + 1;
                if (c0 > qg0) accS[nt][0] = -1e30f;
                if (c1 > qg0) accS[nt][1] = -1e30f;
                if (c0 > qg1) accS[nt][2] = -1e30f;
                if (c1 > qg1) accS[nt][3] = -1e30f;
            }
        }

        float mx0 = accS[0][0], mx1 = accS[0][2];
#pragma unroll
        for (int nt = 0; nt < 8; nt++) {
            mx0 = fmaxf(mx0, fmaxf(accS[nt][0], accS[nt][1]));
            mx1 = fmaxf(mx1, fmaxf(accS[nt][2], accS[nt][3]));
        }
        mx0 = fmaxf(mx0, __shfl_xor_sync(0xffffffffu, mx0, 1));
        mx0 = fmaxf(mx0, __shfl_xor_sync(0xffffffffu, mx0, 2));
        mx1 = fmaxf(mx1, __shfl_xor_sync(0xffffffffu, mx1, 1));
        mx1 = fmaxf(mx1, __shfl_xor_sync(0xffffffffu, mx1, 2));
        float nm0 = fmaxf(m0, mx0), nm1 = fmaxf(m1, mx1);
        float corr0 = __expf(m0 - nm0), corr1 = __expf(m1 - nm1);
        m0 = nm0; m1 = nm1;

        float rs0 = 0.f, rs1 = 0.f;
        uint32_t aPh[4][4], aPl[4][4];
#pragma unroll
        for (int nt = 0; nt < 8; nt++) {
            float p0 = __expf(accS[nt][0] - m0);
            float p1 = __expf(accS[nt][1] - m0);
            float p2 = __expf(accS[nt][2] - m1);
            float p3 = __expf(accS[nt][3] - m1);
            rs0 += p0 + p1; rs1 += p2 + p3;
            const int i0 = (nt & 1) * 2;
            aPh[nt >> 1][i0 + 0] = pksplit(p0, p1, aPl[nt >> 1][i0 + 0]);
            aPh[nt >> 1][i0 + 1] = pksplit(p2, p3, aPl[nt >> 1][i0 + 1]);
        }
        rs0 += __shfl_xor_sync(0xffffffffu, rs0, 1);
        rs0 += __shfl_xor_sync(0xffffffffu, rs0, 2);
        rs1 += __shfl_xor_sync(0xffffffffu, rs1, 1);
        rs1 += __shfl_xor_sync(0xffffffffu, rs1, 2);
        l0 = l0 * corr0 + rs0;
        l1 = l1 * corr1 + rs1;

#pragma unroll
        for (int nt = 0; nt < 12; nt++) {
            accO[nt][0] *= corr0; accO[nt][1] *= corr0;
            accO[nt][2] *= corr1; accO[nt][3] *= corr1;
        }

#pragma unroll
        for (int kt2 = 0; kt2 < 4; kt2++) {
            const uint32_t toff = (uint32_t)(kt2 * 16 * 208);
            uint32_t a0 = aPh[kt2][0], a1 = aPh[kt2][1], a2 = aPh[kt2][2], a3 = aPh[kt2][3];
            uint32_t c0 = aPl[kt2][0], c1 = aPl[kt2][1], c2 = aPl[kt2][2], c3 = aPl[kt2][3];
#pragma unroll
            for (int p = 0; p < 6; p++) {
                const uint32_t off = toff + (uint32_t)(p * 32);
                uint32_t bh0, bh1, bh2, bh3, bl0, bl1, bl2, bl3;
                ldm_x4_t(bh0, bh1, bh2, bh3, vh_b + off);
                ldm_x4_t(bl0, bl1, bl2, bl3, vl_b + off);
                const int n0 = 2 * p, n1 = 2 * p + 1;
                mma_bf16(accO[n0][0], accO[n0][1], accO[n0][2], accO[n0][3],
                         a0, a1, a2, a3, bh0, bh1);
                mma_bf16(accO[n0][0], accO[n0][1], accO[n0][2], accO[n0][3],
                         a0, a1, a2, a3, bl0, bl1);
                mma_bf16(accO[n0][0], accO[n0][1], accO[n0][2], accO[n0][3],
                         c0, c1, c2, c3, bh0, bh1);
                mma_bf16(accO[n1][0], accO[n1][1], accO[n1][2], accO[n1][3],
                         a0, a1, a2, a3, bh2, bh3);
                mma_bf16(accO[n1][0], accO[n1][1], accO[n1][2], accO[n1][3],
                         a0, a1, a2, a3, bl2, bl3);
                mma_bf16(accO[n1][0], accO[n1][1], accO[n1][2], accO[n1][3],
                         c0, c1, c2, c3, bh2, bh3);
            }
        }
        __syncthreads();
        if (kt + 2 < nkt) issue_tile(kt + 2, kt & 1);
    }

    const float inv0 = 1.f / l0;
    const float inv1 = 1.f / l1;
    const size_t grow0 = (size_t)(b * T_SEQ + qtp * 128 + r0l);
    const size_t grow1 = grow0 + 8;
#pragma unroll
    for (int nt = 0; nt < 12; nt++) {
        const int col = h * HD + nt * 8 + 2 * lc;
        uint32_t lo0, lo1;
        uint32_t hi0 = pksplit(accO[nt][0] * inv0, accO[nt][1] * inv0, lo0);
        uint32_t hi1 = pksplit(accO[nt][2] * inv1, accO[nt][3] * inv1, lo1);
        *(uint32_t*)(atth + grow0 * C_EMB + col) = hi0;
        *(uint32_t*)(attl + grow0 * C_EMB + col) = lo0;
        *(uint32_t*)(atth + grow1 * C_EMB + col) = hi1;
        *(uint32_t*)(attl + grow1 * C_EMB + col) = lo1;
    }
}

// ---------------------------------------------------------------------------
// Launch
// ---------------------------------------------------------------------------
extern "C" void kernel_launch(void* const* d_in, const int* in_sizes, int n_in,
                              void* d_out, int out_size)
{
    (void)in_sizes; (void)n_in; (void)out_size;
    const float* x  = (const float*)d_in[0];
    const float* w1 = (const float*)d_in[1];
    const float* b1 = (const float*)d_in[2];
    const float* w2 = (const float*)d_in[3];
    const float* b2 = (const float*)d_in[4];
    float* out = (float*)d_out;

    __nv_bfloat16 *xh, *xl, *w1h, *w1l, *w2h, *w2l, *qh, *ql, *ah, *al;
    cudaGetSymbolAddress((void**)&xh, g_xh);
    cudaGetSymbolAddress((void**)&xl, g_xl);
    cudaGetSymbolAddress((void**)&w1h, g_w1h);
    cudaGetSymbolAddress((void**)&w1l, g_w1l);
    cudaGetSymbolAddress((void**)&w2h, g_w2h);
    cudaGetSymbolAddress((void**)&w2l, g_w2l);
    cudaGetSymbolAddress((void**)&qh, g_qkvh);
    cudaGetSymbolAddress((void**)&ql, g_qkvl);
    cudaGetSymbolAddress((void**)&ah, g_atth);
    cudaGetSymbolAddress((void**)&al, g_attl);

    cudaFuncSetAttribute(gemm_mma<true>,
                         cudaFuncAttributeMaxDynamicSharedMemorySize, GEMM_SMEM_BYTES);
    cudaFuncSetAttribute(gemm_mma<false>,
                         cudaFuncAttributeMaxDynamicSharedMemorySize, GEMM_SMEM_BYTES);
    cudaFuncSetAttribute(flash_mma,
                         cudaFuncAttributeMaxDynamicSharedMemorySize, FL_SMEM_BYTES);

    // pre-split inputs
    split_f32<<<256, 256>>>(x,  xh,  xl,  M_ROWS * C_EMB / 4);
    split_f32<<<256, 256>>>(w1, w1h, w1l, 3 * C_EMB * C_EMB / 4);
    split_f32<<<64,  256>>>(w2, w2h, w2l, C_EMB * C_EMB / 4);

    // QKV projection -> split qkv
    gemm_mma<true><<<dim3(3 * C_EMB / 128, M_ROWS / 64), 128, GEMM_SMEM_BYTES>>>(
        xh, xl, w1h, w1l, b1, nullptr, qh, ql, 3 * C_EMB);

    // Causal attention -> split att
    flash_mma<<<dim3(T_SEQ / 128, NH, BATCH), 256, FL_SMEM_BYTES>>>(qh, ql, ah, al);

    // Output projection -> fp32 out
    gemm_mma<false><<<dim3(C_EMB / 128, M_ROWS / 64), 128, GEMM_SMEM_BYTES>>>(
        ah, al, w2h, w2l, b2, out, nullptr, nullptr, C_EMB);
}

// round 10
// speedup vs baseline: 1.5633x; 1.5633x over previous
#include <cuda_runtime.h>
#include <cuda_bf16.h>
#include <math.h>
#include <stdint.h>

// Problem constants
#define BATCH 8
#define T_SEQ 1024
#define C_EMB 768
#define NH    8
#define HD    96
#define M_ROWS (BATCH * T_SEQ)   // 8192
#define GK    768

// ---------------------------------------------------------------------------
// Scratch: pre-split bf16 hi/lo arrays
// ---------------------------------------------------------------------------
__device__ __nv_bfloat16 g_xh[(size_t)M_ROWS * C_EMB];
__device__ __nv_bfloat16 g_xl[(size_t)M_ROWS * C_EMB];
__device__ __nv_bfloat16 g_w1h[(size_t)3 * C_EMB * C_EMB];
__device__ __nv_bfloat16 g_w1l[(size_t)3 * C_EMB * C_EMB];
__device__ __nv_bfloat16 g_w2h[(size_t)C_EMB * C_EMB];
__device__ __nv_bfloat16 g_w2l[(size_t)C_EMB * C_EMB];
__device__ __nv_bfloat16 g_qkvh[(size_t)M_ROWS * 3 * C_EMB];
__device__ __nv_bfloat16 g_qkvl[(size_t)M_ROWS * 3 * C_EMB];
__device__ __nv_bfloat16 g_atth[(size_t)M_ROWS * C_EMB];
__device__ __nv_bfloat16 g_attl[(size_t)M_ROWS * C_EMB];

// ---------------------------------------------------------------------------
// PTX helpers (baseline ISA at compute_103)
// ---------------------------------------------------------------------------
__device__ __forceinline__ uint32_t smem_u32(const void* p) {
    uint32_t a;
    asm("{ .reg .u64 t; cvta.to.shared.u64 t, %1; cvt.u32.u64 %0, t; }"
        : "=r"(a) : "l"(p));
    return a;
}
__device__ __forceinline__ void mma_bf16(
    float& c0, float& c1, float& c2, float& c3,
    uint32_t a0, uint32_t a1, uint32_t a2, uint32_t a3,
    uint32_t b0, uint32_t b1)
{
    asm volatile(
        "mma.sync.aligned.m16n8k16.row.col.f32.bf16.bf16.f32 "
        "{%0,%1,%2,%3}, {%4,%5,%6,%7}, {%8,%9}, {%0,%1,%2,%3};"
        : "+f"(c0), "+f"(c1), "+f"(c2), "+f"(c3)
        : "r"(a0), "r"(a1), "r"(a2), "r"(a3), "r"(b0), "r"(b1));
}
__device__ __forceinline__ void ldm_x4(
    uint32_t& r0, uint32_t& r1, uint32_t& r2, uint32_t& r3, uint32_t saddr)
{
    asm volatile("ldmatrix.sync.aligned.m8n8.x4.shared.b16 {%0,%1,%2,%3}, [%4];"
        : "=r"(r0), "=r"(r1), "=r"(r2), "=r"(r3) : "r"(saddr));
}
__device__ __forceinline__ void ldm_x4_t(
    uint32_t& r0, uint32_t& r1, uint32_t& r2, uint32_t& r3, uint32_t saddr)
{
    asm volatile("ldmatrix.sync.aligned.m8n8.x4.trans.shared.b16 {%0,%1,%2,%3}, [%4];"
        : "=r"(r0), "=r"(r1), "=r"(r2), "=r"(r3) : "r"(saddr));
}
__device__ __forceinline__ void cp16(uint32_t dst, const void* src) {
    asm volatile("cp.async.cg.shared.global [%0], [%1], 16;"
        :: "r"(dst), "l"(src) : "memory");
}
#define CP_COMMIT() asm volatile("cp.async.commit_group;" ::: "memory")
#define CP_WAIT0()  asm volatile("cp.async.wait_group 0;" ::: "memory")
#define CP_WAIT1()  asm volatile("cp.async.wait_group 1;" ::: "memory")

__device__ __forceinline__ uint32_t pkbf(__nv_bfloat16 a, __nv_bfloat16 b) {
    __nv_bfloat162 t(a, b);
    return *reinterpret_cast<uint32_t*>(&t);
}
__device__ __forceinline__ uint32_t pkf2(float a, float b) {
    __nv_bfloat162 t = __float22bfloat162_rn(make_float2(a, b));
    return *reinterpret_cast<uint32_t*>(&t);
}
__device__ __forceinline__ uint32_t pksplit(float a, float b, uint32_t& lo) {
    __nv_bfloat16 ha = __float2bfloat16_rn(a);
    __nv_bfloat16 hb = __float2bfloat16_rn(b);
    lo = pkf2(a - __bfloat162float(ha), b - __bfloat162float(hb));
    return pkbf(ha, hb);
}

// ---------------------------------------------------------------------------
// Pre-split fp32 -> bf16 hi/lo (elementwise)
// ---------------------------------------------------------------------------
__global__ void split_f32(const float* __restrict__ s,
                          __nv_bfloat16* __restrict__ h,
                          __nv_bfloat16* __restrict__ l, int n4)
{
    int i = blockIdx.x * blockDim.x + threadIdx.x;
    int stride = gridDim.x * blockDim.x;
    for (; i < n4; i += stride) {
        float4 v = ((const float4*)s)[i];
        uint32_t l0, l1;
        uint32_t h0 = pksplit(v.x, v.y, l0);
        uint32_t h1 = pksplit(v.z, v.w, l1);
        ((uint2*)h)[i] = make_uint2(h0, h1);
        ((uint2*)l)[i] = make_uint2(l0, l1);
    }
}

// ---------------------------------------------------------------------------
// Split-bf16 GEMM (R8 config: pad-40 smem, 3 CTAs/SM) with product-pass
// reordering: hh x16, hl x16, lh x16 per k-step (acc reuse distance 16).
// ---------------------------------------------------------------------------
#define AS_STRIDE 40
#define ABUF (64 * AS_STRIDE)
#define BBUF (128 * AS_STRIDE)
#define BUFSZ (2 * ABUF + 2 * BBUF)
#define GEMM_SMEM_BYTES (2 * BUFSZ * 2)
#define NCHUNK (GK / 32)

template <bool SPLIT_OUT>
__global__ __launch_bounds__(128, 3) void gemm_mma(
    const __nv_bfloat16* __restrict__ Ahg, const __nv_bfloat16* __restrict__ Alg,
    const __nv_bfloat16* __restrict__ Bhg, const __nv_bfloat16* __restrict__ Blg,
    const float* __restrict__ bias,
    float* __restrict__ Cf,
    __nv_bfloat16* __restrict__ Ch, __nv_bfloat16* __restrict__ Cl,
    int N)
{
    extern __shared__ __nv_bfloat16 smb[];

    const int tid  = threadIdx.x;
    const int w    = tid >> 5;
    const int lane = tid & 31;
    const int gr   = lane >> 2;
    const int lc   = lane & 3;
    const int bm   = blockIdx.y * 64;
    const int bn   = blockIdx.x * 128;

    const uint32_t smbase = smem_u32(smb);
    const uint32_t aoff = (((lane & 15) * AS_STRIDE) + ((lane >> 4) << 3)) * 2;
    const uint32_t boff = (((w * 32) + ((lane >> 4) << 3) + (lane & 7)) * AS_STRIDE) * 2
                          + ((lane >> 3) & 1) * 16;

    const int ar = tid >> 2, ack = tid & 3;

    auto issue_chunk = [&](int t, int buf) {
        const uint32_t bb = smbase + (uint32_t)(buf * (BUFSZ * 2));
        const int k0 = t * 32;
#pragma unroll
        for (int j = 0; j < 2; j++) {
            int r = ar + 32 * j;
            const size_t so = (size_t)(bm + r) * GK + k0 + ack * 8;
            uint32_t d = bb + (uint32_t)(r * 80 + ack * 16);
            cp16(d, Ahg + so);
            cp16(d + ABUF * 2, Alg + so);
        }
#pragma unroll
        for (int j = 0; j < 4; j++) {
            int r = ar + 32 * j;
            const size_t so = (size_t)(bn + r) * GK + k0 + ack * 8;
            uint32_t d = bb + (uint32_t)(2 * ABUF * 2 + r * 80 + ack * 16);
            cp16(d, Bhg + so);
            cp16(d + BBUF * 2, Blg + so);
        }
        CP_COMMIT();
    };

    float acc[4][4][4];
#pragma unroll
    for (int mt = 0; mt < 4; mt++)
#pragma unroll
        for (int nt = 0; nt < 4; nt++)
#pragma unroll
            for (int r = 0; r < 4; r++) acc[mt][nt][r] = 0.f;

    issue_chunk(0, 0);
    issue_chunk(1, 1);

    for (int t = 0; t < NCHUNK; t++) {
        if (t + 1 < NCHUNK) { CP_WAIT1(); } else { CP_WAIT0(); }
        __syncthreads();

        {
            const uint32_t bufb = smbase + (uint32_t)((t & 1) * (BUFSZ * 2));
            const uint32_t ah_b = bufb + aoff;
            const uint32_t al_b = ah_b + ABUF * 2;
            const uint32_t bh_b = bufb + (2 * ABUF) * 2 + boff;
            const uint32_t bl_b = bh_b + BBUF * 2;

#pragma unroll
            for (int ks = 0; ks < 2; ks++) {
                const uint32_t kbb = (uint32_t)(ks * 32);
                uint32_t af[4][4], bhf[4][2], blf[4][2];
#pragma unroll
                for (int mt = 0; mt < 4; mt++)
                    ldm_x4(af[mt][0], af[mt][1], af[mt][2], af[mt][3],
                           ah_b + (uint32_t)(mt * 16 * AS_STRIDE * 2) + kbb);
#pragma unroll
                for (int p = 0; p < 2; p++) {
                    uint32_t base = (uint32_t)(p * 16 * AS_STRIDE * 2) + kbb;
                    ldm_x4(bhf[2 * p][0], bhf[2 * p][1], bhf[2 * p + 1][0], bhf[2 * p + 1][1],
                           bh_b + base);
                    ldm_x4(blf[2 * p][0], blf[2 * p][1], blf[2 * p + 1][0], blf[2 * p + 1][1],
                           bl_b + base);
                }
                // pass 1: Ah*Bh (16 independent accs)
#pragma unroll
                for (int mt = 0; mt < 4; mt++)
#pragma unroll
                    for (int nt = 0; nt < 4; nt++)
                        mma_bf16(acc[mt][nt][0], acc[mt][nt][1],
                                 acc[mt][nt][2], acc[mt][nt][3],
                                 af[mt][0], af[mt][1], af[mt][2], af[mt][3],
                                 bhf[nt][0], bhf[nt][1]);
                // pass 2: Ah*Bl
#pragma unroll
                for (int mt = 0; mt < 4; mt++)
#pragma unroll
                    for (int nt = 0; nt < 4; nt++)
                        mma_bf16(acc[mt][nt][0], acc[mt][nt][1],
                                 acc[mt][nt][2], acc[mt][nt][3],
                                 af[mt][0], af[mt][1], af[mt][2], af[mt][3],
                                 blf[nt][0], blf[nt][1]);
                // pass 3: Al*Bh
#pragma unroll
                for (int mt = 0; mt < 4; mt++)
                    ldm_x4(af[mt][0], af[mt][1], af[mt][2], af[mt][3],
                           al_b + (uint32_t)(mt * 16 * AS_STRIDE * 2) + kbb);
#pragma unroll
                for (int mt = 0; mt < 4; mt++)
#pragma unroll
                    for (int nt = 0; nt < 4; nt++)
                        mma_bf16(acc[mt][nt][0], acc[mt][nt][1],
                                 acc[mt][nt][2], acc[mt][nt][3],
                                 af[mt][0], af[mt][1], af[mt][2], af[mt][3],
                                 bhf[nt][0], bhf[nt][1]);
            }
        }
        __syncthreads();
        if (t + 2 < NCHUNK) issue_chunk(t + 2, t & 1);
    }

    // epilogue
#pragma unroll
    for (int nt = 0; nt < 4; nt++) {
        const int col = bn + w * 32 + nt * 8 + lc * 2;
        const float2 bj = *(const float2*)(bias + col);
#pragma unroll
        for (int mt = 0; mt < 4; mt++) {
            const int row0 = bm + mt * 16 + gr;
            float x0 = acc[mt][nt][0] + bj.x, y0 = acc[mt][nt][1] + bj.y;
            float x1 = acc[mt][nt][2] + bj.x, y1 = acc[mt][nt][3] + bj.y;
            if (SPLIT_OUT) {
                uint32_t lo0, lo1;
                uint32_t hi0 = pksplit(x0, y0, lo0);
                uint32_t hi1 = pksplit(x1, y1, lo1);
                *(uint32_t*)(Ch + (size_t)row0 * N + col) = hi0;
                *(uint32_t*)(Cl + (size_t)row0 * N + col) = lo0;
                *(uint32_t*)(Ch + (size_t)(row0 + 8) * N + col) = hi1;
                *(uint32_t*)(Cl + (size_t)(row0 + 8) * N + col) = lo1;
            } else {
                *(float2*)(Cf + (size_t)row0 * N + col) = make_float2(x0, y0);
                *(float2*)(Cf + (size_t)(row0 + 8) * N + col) = make_float2(x1, y1);
            }
        }
    }
}

// ---------------------------------------------------------------------------
// Flash attention (R8 structure) with product-pass reordering in QK and PV.
// ---------------------------------------------------------------------------
#define FKST 104
#define FBUF_B (64 * FKST * 2)
#define FBUF_TOTAL (4 * FBUF_B)
#define FL_SMEM_BYTES (2 * FBUF_TOTAL)

__global__ __launch_bounds__(256, 1) void flash_mma(
    const __nv_bfloat16* __restrict__ qkvh,
    const __nv_bfloat16* __restrict__ qkvl,
    __nv_bfloat16* __restrict__ atth,
    __nv_bfloat16* __restrict__ attl)
{
    extern __shared__ char fsm[];
    const uint32_t smbase = smem_u32(fsm);

    const int qtp = 7 - (int)blockIdx.x;
    const int h   = blockIdx.y;
    const int b   = blockIdx.z;
    const int tid  = threadIdx.x;
    const int w    = tid >> 5;
    const int lane = tid & 31;
    const int gr   = lane >> 2;
    const int lc   = lane & 3;
    const int r0l  = w * 16 + gr;
    const int r1l  = r0l + 8;

    const int nkt = 2 * qtp + 2;
    const float rscale = 0.10206207261596577f;

    auto issue_tile = [&](int kt, int buf) {
        const uint32_t bb = smbase + (uint32_t)(buf * FBUF_TOTAL);
        const size_t rowbase = (size_t)(b * T_SEQ + kt * 64);
        const size_t koff = (size_t)C_EMB + h * HD;
        const size_t voff = (size_t)2 * C_EMB + h * HD;
#pragma unroll
        for (int j = 0; j < 3; j++) {
            int i = tid + 256 * j;
            int r = i / 12, ck = i % 12;
            const size_t so = (rowbase + r) * (3 * C_EMB) + ck * 8;
            uint32_t d = bb + (uint32_t)(r * 208 + ck * 16);
            cp16(d, qkvh + so + koff);
            cp16(d + FBUF_B, qkvl + so + koff);
            cp16(d + 2 * FBUF_B, qkvh + so + voff);
            cp16(d + 3 * FBUF_B, qkvl + so + voff);
        }
        CP_COMMIT();
    };

    issue_tile(0, 0);

    {
        const uint32_t qb = smbase + FBUF_TOTAL;
        const size_t rowbase = (size_t)(b * T_SEQ + qtp * 128);
        const size_t qoff = (size_t)h * HD;
#pragma unroll
        for (int j = 0; j < 6; j++) {
            int i = tid + 256 * j;
            int r = i / 12, ck = i % 12;
            const size_t so = (rowbase + r) * (3 * C_EMB) + qoff + ck * 8;
            uint32_t d = qb + (uint32_t)(r * 208 + ck * 16);
            *(uint4*)(fsm + (d - smbase)) = *(const uint4*)(qkvh + so);
            *(uint4*)(fsm + (d - smbase) + 26624) = *(const uint4*)(qkvl + so);
        }
    }
    __syncthreads();

    uint32_t Qhf[6][4], Qlf[6][4];
    {
        const uint32_t afl = (uint32_t)((lane & 15) * 208 + ((lane >> 4) << 4));
        const uint32_t qh_b = smbase + FBUF_TOTAL + (uint32_t)(w * 16 * 208) + afl;
#pragma unroll
        for (int ks = 0; ks < 6; ks++) {
            ldm_x4(Qhf[ks][0], Qhf[ks][1], Qhf[ks][2], Qhf[ks][3], qh_b + ks * 32);
            ldm_x4(Qlf[ks][0], Qlf[ks][1], Qlf[ks][2], Qlf[ks][3], qh_b + 26624 + ks * 32);
        }
    }
    __syncthreads();
    issue_tile(1, 1);

    const uint32_t kfl = (uint32_t)((((lane >> 4) << 3) + (lane & 7)) * 208
                                    + ((lane >> 3) & 1) * 16);
    const uint32_t vfl = (uint32_t)((lane & 15) * 208 + ((lane >> 4) << 4));

    float accO[12][4];
#pragma unroll
    for (int nt = 0; nt < 12; nt++)
#pragma unroll
        for (int r = 0; r < 4; r++) accO[nt][r] = 0.f;
    float m0 = -1e30f, m1 = -1e30f, l0 = 0.f, l1 = 0.f;

    for (int kt = 0; kt < nkt; kt++) {
        if (kt + 1 < nkt) { CP_WAIT1(); } else { CP_WAIT0(); }
        __syncthreads();

        const uint32_t bb = smbase + (uint32_t)((kt & 1) * FBUF_TOTAL);
        const uint32_t kh_b = bb + kfl;
        const uint32_t kl_b = kh_b + FBUF_B;
        const uint32_t vh_b = bb + 2 * FBUF_B + vfl;
        const uint32_t vl_b = vh_b + FBUF_B;

        float accS[8][4];
#pragma unroll
        for (int nt = 0; nt < 8; nt++)
#pragma unroll
            for (int r = 0; r < 4; r++) accS[nt][r] = 0.f;

#pragma unroll
        for (int ks = 0; ks < 6; ks++) {
            const uint32_t kxb = (uint32_t)(ks * 32);
            uint32_t bh[8][2], bl[8][2];
#pragma unroll
            for (int p = 0; p < 4; p++) {
                uint32_t off = (uint32_t)(p * 16 * 208) + kxb;
                ldm_x4(bh[2 * p][0], bh[2 * p][1], bh[2 * p + 1][0], bh[2 * p + 1][1],
                       kh_b + off);
                ldm_x4(bl[2 * p][0], bl[2 * p][1], bl[2 * p + 1][0], bl[2 * p + 1][1],
                       kl_b + off);
            }
            // pass 1: Qh*Kh (8 independent accs)
#pragma unroll
            for (int nt = 0; nt < 8; nt++)
                mma_bf16(accS[nt][0], accS[nt][1], accS[nt][2], accS[nt][3],
                         Qhf[ks][0], Qhf[ks][1], Qhf[ks][2], Qhf[ks][3],
                         bh[nt][0], bh[nt][1]);
            // pass 2: Qh*Kl
#pragma unroll
            for (int nt = 0; nt < 8; nt++)
                mma_bf16(accS[nt][0], accS[nt][1], accS[nt][2], accS[nt][3],
                         Qhf[ks][0], Qhf[ks][1], Qhf[ks][2], Qhf[ks][3],
                         bl[nt][0], bl[nt][1]);
            // pass 3: Ql*Kh
#pragma unroll
            for (int nt = 0; nt < 8; nt++)
                mma_bf16(accS[nt][0], accS[nt][1], accS[nt][2], accS[nt][3],
                         Qlf[ks][0], Qlf[ks][1], Qlf[ks][2], Qlf[ks][3],
                         bh[nt][0], bh[nt][1]);
        }

#pragma unroll
        for (int nt = 0; nt < 8; nt++)
#pragma unroll
            for (int r = 0; r < 4; r++) accS[nt][r] *= rscale;

        if (kt >= 2 * qtp) {
            const int qg0 = qtp * 128 + r0l;
            const int qg1 = qg0 + 8;
#pragma unroll
            for (int nt = 0; nt < 8; nt++) {
                int c0 = kt * 64 + nt * 8 + 2 * lc, c1 = c0 + 1;
                if (c0 > qg0) accS[nt][0] = -1e30f;
                if (c1 > qg0) accS[nt][1] = -1e30f;
                if (c0 > qg1) accS[nt][2] = -1e30f;
                if (c1 > qg1) accS[nt][3] = -1e30f;
            }
        }

        float mx0 = accS[0][0], mx1 = accS[0][2];
#pragma unroll
        for (int nt = 0; nt < 8; nt++) {
            mx0 = fmaxf(mx0, fmaxf(accS[nt][0], accS[nt][1]));
            mx1 = fmaxf(mx1, fmaxf(accS[nt][2], accS[nt][3]));
        }
        mx0 = fmaxf(mx0, __shfl_xor_sync(0xffffffffu, mx0, 1));
        mx0 = fmaxf(mx0, __shfl_xor_sync(0xffffffffu, mx0, 2));
        mx1 = fmaxf(mx1, __shfl_xor_sync(0xffffffffu, mx1, 1));
        mx1 = fmaxf(mx1, __shfl_xor_sync(0xffffffffu, mx1, 2));
        float nm0 = fmaxf(m0, mx0), nm1 = fmaxf(m1, mx1);
        float corr0 = __expf(m0 - nm0), corr1 = __expf(m1 - nm1);
        m0 = nm0; m1 = nm1;

        float rs0 = 0.f, rs1 = 0.f;
        uint32_t aPh[4][4], aPl[4][4];
#pragma unroll
        for (int nt = 0; nt < 8; nt++) {
            float p0 = __expf(accS[nt][0] - m0);
            float p1 = __expf(accS[nt][1] - m0);
            float p2 = __expf(accS[nt][2] - m1);
            float p3 = __expf(accS[nt][3] - m1);
            rs0 += p0 + p1; rs1 += p2 + p3;
            const int i0 = (nt & 1) * 2;
            aPh[nt >> 1][i0 + 0] = pksplit(p0, p1, aPl[nt >> 1][i0 + 0]);
            aPh[nt >> 1][i0 + 1] = pksplit(p2, p3, aPl[nt >> 1][i0 + 1]);
        }
        rs0 += __shfl_xor_sync(0xffffffffu, rs0, 1);
        rs0 += __shfl_xor_sync(0xffffffffu, rs0, 2);
        rs1 += __shfl_xor_sync(0xffffffffu, rs1, 1);
        rs1 += __shfl_xor_sync(0xffffffffu, rs1, 2);
        l0 = l0 * corr0 + rs0;
        l1 = l1 * corr1 + rs1;

#pragma unroll
        for (int nt = 0; nt < 12; nt++) {
            accO[nt][0] *= corr0; accO[nt][1] *= corr0;
            accO[nt][2] *= corr1; accO[nt][3] *= corr1;
        }

        // ---- O += P V: hoist V hi frags, 2 passes, then lo frags, 1 pass ----
#pragma unroll
        for (int kt2 = 0; kt2 < 4; kt2++) {
            const uint32_t toff = (uint32_t)(kt2 * 16 * 208);
            uint32_t a0 = aPh[kt2][0], a1 = aPh[kt2][1], a2 = aPh[kt2][2], a3 = aPh[kt2][3];
            uint32_t c0 = aPl[kt2][0], c1 = aPl[kt2][1], c2 = aPl[kt2][2], c3 = aPl[kt2][3];
            uint32_t vf[6][4];
#pragma unroll
            for (int p = 0; p < 6; p++)
                ldm_x4_t(vf[p][0], vf[p][1], vf[p][2], vf[p][3],
                         vh_b + toff + (uint32_t)(p * 32));
            // pass 1: Ph*Vh (12 independent accs)
#pragma unroll
            for (int p = 0; p < 6; p++) {
                mma_bf16(accO[2*p][0], accO[2*p][1], accO[2*p][2], accO[2*p][3],
                         a0, a1, a2, a3, vf[p][0], vf[p][1]);
                mma_bf16(accO[2*p+1][0], accO[2*p+1][1], accO[2*p+1][2], accO[2*p+1][3],
                         a0, a1, a2, a3, vf[p][2], vf[p][3]);
            }
            // pass 2: Pl*Vh
#pragma unroll
            for (int p = 0; p < 6; p++) {
                mma_bf16(accO[2*p][0], accO[2*p][1], accO[2*p][2], accO[2*p][3],
                         c0, c1, c2, c3, vf[p][0], vf[p][1]);
                mma_bf16(accO[2*p+1][0], accO[2*p+1][1], accO[2*p+1][2], accO[2*p+1][3],
                         c0, c1, c2, c3, vf[p][2], vf[p][3]);
            }
            // pass 3: Ph*Vl (reload frags as lo)
#pragma unroll
            for (int p = 0; p < 6; p++)
                ldm_x4_t(vf[p][0], vf[p][1], vf[p][2], vf[p][3],
                         vl_b + toff + (uint32_t)(p * 32));
#pragma unroll
            for (int p = 0; p < 6; p++) {
                mma_bf16(accO[2*p][0], accO[2*p][1], accO[2*p][2], accO[2*p][3],
                         a0, a1, a2, a3, vf[p][0], vf[p][1]);
                mma_bf16(accO[2*p+1][0], accO[2*p+1][1], accO[2*p+1][2], accO[2*p+1][3],
                         a0, a1, a2, a3, vf[p][2], vf[p][3]);
            }
        }
        __syncthreads();
        if (kt + 2 < nkt) issue_tile(kt + 2, kt & 1);
    }

    const float inv0 = 1.f / l0;
    const float inv1 = 1.f / l1;
    const size_t grow0 = (size_t)(b * T_SEQ + qtp * 128 + r0l);
    const size_t grow1 = grow0 + 8;
#pragma unroll
    for (int nt = 0; nt < 12; nt++) {
        const int col = h * HD + nt * 8 + 2 * lc;
        uint32_t lo0, lo1;
        uint32_t hi0 = pksplit(accO[nt][0] * inv0, accO[nt][1] * inv0, lo0);
        uint32_t hi1 = pksplit(accO[nt][2] * inv1, accO[nt][3] * inv1, lo1);
        *(uint32_t*)(atth + grow0 * C_EMB + col) = hi0;
        *(uint32_t*)(attl + grow0 * C_EMB + col) = lo0;
        *(uint32_t*)(atth + grow1 * C_EMB + col) = hi1;
        *(uint32_t*)(attl + grow1 * C_EMB + col) = lo1;
    }
}

// ---------------------------------------------------------------------------
// Launch
// ---------------------------------------------------------------------------
extern "C" void kernel_launch(void* const* d_in, const int* in_sizes, int n_in,
                              void* d_out, int out_size)
{
    (void)in_sizes; (void)n_in; (void)out_size;
    const float* x  = (const float*)d_in[0];
    const float* w1 = (const float*)d_in[1];
    const float* b1 = (const float*)d_in[2];
    const float* w2 = (const float*)d_in[3];
    const float* b2 = (const float*)d_in[4];
    float* out = (float*)d_out;

    __nv_bfloat16 *xh, *xl, *w1h, *w1l, *w2h, *w2l, *qh, *ql, *ah, *al;
    cudaGetSymbolAddress((void**)&xh, g_xh);
    cudaGetSymbolAddress((void**)&xl, g_xl);
    cudaGetSymbolAddress((void**)&w1h, g_w1h);
    cudaGetSymbolAddress((void**)&w1l, g_w1l);
    cudaGetSymbolAddress((void**)&w2h, g_w2h);
    cudaGetSymbolAddress((void**)&w2l, g_w2l);
    cudaGetSymbolAddress((void**)&qh, g_qkvh);
    cudaGetSymbolAddress((void**)&ql, g_qkvl);
    cudaGetSymbolAddress((void**)&ah, g_atth);
    cudaGetSymbolAddress((void**)&al, g_attl);

    cudaFuncSetAttribute(gemm_mma<true>,
                         cudaFuncAttributeMaxDynamicSharedMemorySize, GEMM_SMEM_BYTES);
    cudaFuncSetAttribute(gemm_mma<false>,
                         cudaFuncAttributeMaxDynamicSharedMemorySize, GEMM_SMEM_BYTES);
    cudaFuncSetAttribute(flash_mma,
                         cudaFuncAttributeMaxDynamicSharedMemorySize, FL_SMEM_BYTES);

    // pre-split inputs
    split_f32<<<256, 256>>>(x,  xh,  xl,  M_ROWS * C_EMB / 4);
    split_f32<<<256, 256>>>(w1, w1h, w1l, 3 * C_EMB * C_EMB / 4);
    split_f32<<<64,  256>>>(w2, w2h, w2l, C_EMB * C_EMB / 4);

    // QKV projection -> split qkv
    gemm_mma<true><<<dim3(3 * C_EMB / 128, M_ROWS / 64), 128, GEMM_SMEM_BYTES>>>(
        xh, xl, w1h, w1l, b1, nullptr, qh, ql, 3 * C_EMB);

    // Causal attention -> split att
    flash_mma<<<dim3(T_SEQ / 128, NH, BATCH), 256, FL_SMEM_BYTES>>>(qh, ql, ah, al);

    // Output projection -> fp32 out
    gemm_mma<false><<<dim3(C_EMB / 128, M_ROWS / 64), 128, GEMM_SMEM_BYTES>>>(
        ah, al, w2h, w2l, b2, out, nullptr, nullptr, C_EMB);
}

// round 11
// speedup vs baseline: 3.8012x; 2.4315x over previous
#include <cuda_runtime.h>
#include <cuda_fp16.h>
#include <math.h>
#include <stdint.h>

// Problem constants
#define BATCH 8
#define T_SEQ 1024
#define C_EMB 768
#define NH    8
#define HD    96
#define M_ROWS (BATCH * T_SEQ)   // 8192
#define GK    768

// ---------------------------------------------------------------------------
// Scratch: fp16 arrays
// ---------------------------------------------------------------------------
__device__ __half g_xh[(size_t)M_ROWS * C_EMB];
__device__ __half g_w1h[(size_t)3 * C_EMB * C_EMB];
__device__ __half g_w2h[(size_t)C_EMB * C_EMB];
__device__ __half g_qkvh[(size_t)M_ROWS * 3 * C_EMB];
__device__ __half g_atth[(size_t)M_ROWS * C_EMB];

// ---------------------------------------------------------------------------
// PTX helpers (baseline ISA at compute_103)
// ---------------------------------------------------------------------------
__device__ __forceinline__ uint32_t smem_u32(const void* p) {
    uint32_t a;
    asm("{ .reg .u64 t; cvta.to.shared.u64 t, %1; cvt.u32.u64 %0, t; }"
        : "=r"(a) : "l"(p));
    return a;
}
__device__ __forceinline__ void mma_f16(
    float& c0, float& c1, float& c2, float& c3,
    uint32_t a0, uint32_t a1, uint32_t a2, uint32_t a3,
    uint32_t b0, uint32_t b1)
{
    asm volatile(
        "mma.sync.aligned.m16n8k16.row.col.f32.f16.f16.f32 "
        "{%0,%1,%2,%3}, {%4,%5,%6,%7}, {%8,%9}, {%0,%1,%2,%3};"
        : "+f"(c0), "+f"(c1), "+f"(c2), "+f"(c3)
        : "r"(a0), "r"(a1), "r"(a2), "r"(a3), "r"(b0), "r"(b1));
}
__device__ __forceinline__ void ldm_x4(
    uint32_t& r0, uint32_t& r1, uint32_t& r2, uint32_t& r3, uint32_t saddr)
{
    asm volatile("ldmatrix.sync.aligned.m8n8.x4.shared.b16 {%0,%1,%2,%3}, [%4];"
        : "=r"(r0), "=r"(r1), "=r"(r2), "=r"(r3) : "r"(saddr));
}
__device__ __forceinline__ void ldm_x4_t(
    uint32_t& r0, uint32_t& r1, uint32_t& r2, uint32_t& r3, uint32_t saddr)
{
    asm volatile("ldmatrix.sync.aligned.m8n8.x4.trans.shared.b16 {%0,%1,%2,%3}, [%4];"
        : "=r"(r0), "=r"(r1), "=r"(r2), "=r"(r3) : "r"(saddr));
}
__device__ __forceinline__ void cp16(uint32_t dst, const void* src) {
    asm volatile("cp.async.cg.shared.global [%0], [%1], 16;"
        :: "r"(dst), "l"(src) : "memory");
}
#define CP_COMMIT() asm volatile("cp.async.commit_group;" ::: "memory")
#define CP_WAIT0()  asm volatile("cp.async.wait_group 0;" ::: "memory")
#define CP_WAIT1()  asm volatile("cp.async.wait_group 1;" ::: "memory")

__device__ __forceinline__ uint32_t pkh(float a, float b) {
    __half2 t = __floats2half2_rn(a, b);
    return *reinterpret_cast<uint32_t*>(&t);
}

// ---------------------------------------------------------------------------
// fp32 -> fp16 convert (elementwise)
// ---------------------------------------------------------------------------
__global__ void cvt_f16(const float* __restrict__ s,
                        __half* __restrict__ h, int n4)
{
    int i = blockIdx.x * blockDim.x + threadIdx.x;
    int stride = gridDim.x * blockDim.x;
    for (; i < n4; i += stride) {
        float4 v = ((const float4*)s)[i];
        ((uint2*)h)[i] = make_uint2(pkh(v.x, v.y), pkh(v.z, v.w));
    }
}

// ---------------------------------------------------------------------------
// Single-product fp16 GEMM: C = A * W^T + bias.
// CTA 64x128 (128 thr, 4 warps each 64x32), K chunked 64, double-buffered
// cp.async. Smem row stride 72 halves (144 B; bank offset 4*r, conflict-free).
// ---------------------------------------------------------------------------
#define GST 72                       // halves per smem row
#define GA_B (64 * GST * 2)          // A tile bytes: 9216
#define GB_B (128 * GST * 2)         // B tile bytes: 18432
#define STAGE_B (GA_B + GB_B)        // 27648
#define GEMM_SMEM_BYTES (2 * STAGE_B) // 55296
#define NCHUNK (GK / 64)             // 12

template <bool HALF_OUT>
__global__ __launch_bounds__(128, 4) void gemm_f16(
    const __half* __restrict__ Ag, const __half* __restrict__ Bg,
    const float* __restrict__ bias,
    float* __restrict__ Cf, __half* __restrict__ Chh, int N)
{
    extern __shared__ char smc[];
    const uint32_t smbase = smem_u32(smc);

    const int tid  = threadIdx.x;
    const int w    = tid >> 5;
    const int lane = tid & 31;
    const int gr   = lane >> 2;
    const int lc   = lane & 3;
    const int bm   = blockIdx.y * 64;
    const int bn   = blockIdx.x * 128;

    // fragment address components
    const uint32_t aoff = (uint32_t)((lane & 15) * 144 + ((lane >> 4) << 4));
    const uint32_t boff = (uint32_t)((w * 32 + ((lane >> 4) << 3) + (lane & 7)) * 144
                                     + (((lane >> 3) & 1) << 4));

    auto issue_chunk = [&](int t, int buf) {
        const uint32_t bb = smbase + (uint32_t)(buf * STAGE_B);
        const int k0 = t * 64;
#pragma unroll
        for (int j = 0; j < 4; j++) {              // A: 64 rows x 8 chunks
            int i = tid + 128 * j;
            int r = i >> 3, ck = i & 7;
            cp16(bb + (uint32_t)(r * 144 + ck * 16),
                 Ag + (size_t)(bm + r) * GK + k0 + ck * 8);
        }
#pragma unroll
        for (int j = 0; j < 8; j++) {              // B: 128 rows x 8 chunks
            int i = tid + 128 * j;
            int r = i >> 3, ck = i & 7;
            cp16(bb + GA_B + (uint32_t)(r * 144 + ck * 16),
                 Bg + (size_t)(bn + r) * GK + k0 + ck * 8);
        }
        CP_COMMIT();
    };

    float acc[4][4][4];
#pragma unroll
    for (int mt = 0; mt < 4; mt++)
#pragma unroll
        for (int nt = 0; nt < 4; nt++)
#pragma unroll
            for (int r = 0; r < 4; r++) acc[mt][nt][r] = 0.f;

    issue_chunk(0, 0);
    issue_chunk(1, 1);

    for (int t = 0; t < NCHUNK; t++) {
        if (t + 1 < NCHUNK) { CP_WAIT1(); } else { CP_WAIT0(); }
        __syncthreads();

        {
            const uint32_t bufb = smbase + (uint32_t)((t & 1) * STAGE_B);
            const uint32_t a_b = bufb + aoff;
            const uint32_t b_b = bufb + GA_B + boff;

#pragma unroll
            for (int ks = 0; ks < 4; ks++) {       // 4 x k16 per chunk
                const uint32_t kbb = (uint32_t)(ks * 32);
                uint32_t af[4][4], bf[4][2];
#pragma unroll
                for (int mt = 0; mt < 4; mt++)
                    ldm_x4(af[mt][0], af[mt][1], af[mt][2], af[mt][3],
                           a_b + (uint32_t)(mt * 2304) + kbb);
#pragma unroll
                for (int p = 0; p < 2; p++)
                    ldm_x4(bf[2 * p][0], bf[2 * p][1], bf[2 * p + 1][0], bf[2 * p + 1][1],
                           b_b + (uint32_t)(p * 2304) + kbb);
#pragma unroll
                for (int mt = 0; mt < 4; mt++)
#pragma unroll
                    for (int nt = 0; nt < 4; nt++)
                        mma_f16(acc[mt][nt][0], acc[mt][nt][1],
                                acc[mt][nt][2], acc[mt][nt][3],
                                af[mt][0], af[mt][1], af[mt][2], af[mt][3],
                                bf[nt][0], bf[nt][1]);
            }
        }
        __syncthreads();
        if (t + 2 < NCHUNK) issue_chunk(t + 2, t & 1);
    }

    // epilogue
#pragma unroll
    for (int nt = 0; nt < 4; nt++) {
        const int col = bn + w * 32 + nt * 8 + lc * 2;
        const float2 bj = *(const float2*)(bias + col);
#pragma unroll
        for (int mt = 0; mt < 4; mt++) {
            const int row0 = bm + mt * 16 + gr;
            float x0 = acc[mt][nt][0] + bj.x, y0 = acc[mt][nt][1] + bj.y;
            float x1 = acc[mt][nt][2] + bj.x, y1 = acc[mt][nt][3] + bj.y;
            if (HALF_OUT) {
                *(uint32_t*)(Chh + (size_t)row0 * N + col) = pkh(x0, y0);
                *(uint32_t*)(Chh + (size_t)(row0 + 8) * N + col) = pkh(x1, y1);
            } else {
                *(float2*)(Cf + (size_t)row0 * N + col) = make_float2(x0, y0);
                *(float2*)(Cf + (size_t)(row0 + 8) * N + col) = make_float2(x1, y1);
            }
        }
    }
}

// ---------------------------------------------------------------------------
// Flash attention, single-product fp16. BQ=128 (256 thr, 8 warps x 16 rows),
// cp.async double-buffered K/V (64-token tiles), V row-major + ldmatrix.trans.
// ---------------------------------------------------------------------------
#define FKST 104                       // halves per smem row (208 B)
#define FBUF_B (64 * FKST * 2)         // 13312 B per array
#define FSTAGE (2 * FBUF_B)            // K + V = 26624 B
#define FL_SMEM_BYTES (2 * FSTAGE)     // 53248

__global__ __launch_bounds__(256, 1) void flash_f16(
    const __half* __restrict__ qkvh, __half* __restrict__ atth)
{
    extern __shared__ char fsm[];
    const uint32_t smbase = smem_u32(fsm);

    const int qtp = 7 - (int)blockIdx.x;
    const int h   = blockIdx.y;
    const int b   = blockIdx.z;
    const int tid  = threadIdx.x;
    const int w    = tid >> 5;
    const int lane = tid & 31;
    const int gr   = lane >> 2;
    const int lc   = lane & 3;
    const int r0l  = w * 16 + gr;
    const int r1l  = r0l + 8;

    const int nkt = 2 * qtp + 2;
    const float rscale = 0.10206207261596577f;

    auto issue_tile = [&](int kt, int buf) {
        const uint32_t bb = smbase + (uint32_t)(buf * FSTAGE);
        const size_t rowbase = (size_t)(b * T_SEQ + kt * 64);
        const size_t koff = (size_t)C_EMB + h * HD;
        const size_t voff = (size_t)2 * C_EMB + h * HD;
#pragma unroll
        for (int j = 0; j < 3; j++) {              // 64 rows x 12 chunks each
            int i = tid + 256 * j;
            int r = i / 12, ck = i % 12;
            const size_t so = (rowbase + r) * (3 * C_EMB) + ck * 8;
            uint32_t d = bb + (uint32_t)(r * 208 + ck * 16);
            cp16(d, qkvh + so + koff);             // K
            cp16(d + FBUF_B, qkvh + so + voff);    // V
        }
        CP_COMMIT();
    };

    issue_tile(0, 0);

    {   // stage Q (fp16) into buf1 region (128 rows x 208 B = 26624 B exactly)
        const uint32_t qb = smbase + FSTAGE;
        const size_t rowbase = (size_t)(b * T_SEQ + qtp * 128);
        const size_t qoff = (size_t)h * HD;
#pragma unroll
        for (int j = 0; j < 6; j++) {
            int i = tid + 256 * j;
            int r = i / 12, ck = i % 12;
            const size_t so = (rowbase + r) * (3 * C_EMB) + qoff + ck * 8;
            *(uint4*)(fsm + (qb - smbase) + r * 208 + ck * 16) =
                *(const uint4*)(qkvh + so);
        }
    }
    __syncthreads();

    uint32_t Qf[6][4];
    {
        const uint32_t afl = (uint32_t)((lane & 15) * 208 + ((lane >> 4) << 4));
        const uint32_t qh_b = smbase + FSTAGE + (uint32_t)(w * 16 * 208) + afl;
#pragma unroll
        for (int ks = 0; ks < 6; ks++)
            ldm_x4(Qf[ks][0], Qf[ks][1], Qf[ks][2], Qf[ks][3], qh_b + ks * 32);
    }
    __syncthreads();
    issue_tile(1, 1);

    const uint32_t kfl = (uint32_t)((((lane >> 4) << 3) + (lane & 7)) * 208
                                    + ((lane >> 3) & 1) * 16);
    const uint32_t vfl = (uint32_t)((lane & 15) * 208 + ((lane >> 4) << 4));

    float accO[12][4];
#pragma unroll
    for (int nt = 0; nt < 12; nt++)
#pragma unroll
        for (int r = 0; r < 4; r++) accO[nt][r] = 0.f;
    float m0 = -1e30f, m1 = -1e30f, l0 = 0.f, l1 = 0.f;

    for (int kt = 0; kt < nkt; kt++) {
        if (kt + 1 < nkt) { CP_WAIT1(); } else { CP_WAIT0(); }
        __syncthreads();

        const uint32_t bb = smbase + (uint32_t)((kt & 1) * FSTAGE);
        const uint32_t k_b = bb + kfl;
        const uint32_t v_b = bb + FBUF_B + vfl;

        // ---- S = Q K^T ----
        float accS[8][4];
#pragma unroll
        for (int nt = 0; nt < 8; nt++)
#pragma unroll
            for (int r = 0; r < 4; r++) accS[nt][r] = 0.f;

#pragma unroll
        for (int ks = 0; ks < 6; ks++) {
            const uint32_t kxb = (uint32_t)(ks * 32);
            uint32_t bf[8][2];
#pragma unroll
            for (int p = 0; p < 4; p++)
                ldm_x4(bf[2 * p][0], bf[2 * p][1], bf[2 * p + 1][0], bf[2 * p + 1][1],
                       k_b + (uint32_t)(p * 16 * 208) + kxb);
#pragma unroll
            for (int nt = 0; nt < 8; nt++)
                mma_f16(accS[nt][0], accS[nt][1], accS[nt][2], accS[nt][3],
                        Qf[ks][0], Qf[ks][1], Qf[ks][2], Qf[ks][3],
                        bf[nt][0], bf[nt][1]);
        }

#pragma unroll
        for (int nt = 0; nt < 8; nt++)
#pragma unroll
            for (int r = 0; r < 4; r++) accS[nt][r] *= rscale;

        if (kt >= 2 * qtp) {
            const int qg0 = qtp * 128 + r0l;
            const int qg1 = qg0 + 8;
#pragma unroll
            for (int nt = 0; nt < 8; nt++) {
                int c0 = kt * 64 + nt * 8 + 2 * lc, c1 = c0 + 1;
                if (c0 > qg0) accS[nt][0] = -1e30f;
                if (c1 > qg0) accS[nt][1] = -1e30f;
                if (c0 > qg1) accS[nt][2] = -1e30f;
                if (c1 > qg1) accS[nt][3] = -1e30f;
            }
        }

        // ---- online softmax ----
        float mx0 = accS[0][0], mx1 = accS[0][2];
#pragma unroll
        for (int nt = 0; nt < 8; nt++) {
            mx0 = fmaxf(mx0, fmaxf(accS[nt][0], accS[nt][1]));
            mx1 = fmaxf(mx1, fmaxf(accS[nt][2], accS[nt][3]));
        }
        mx0 = fmaxf(mx0, __shfl_xor_sync(0xffffffffu, mx0, 1));
        mx0 = fmaxf(mx0, __shfl_xor_sync(0xffffffffu, mx0, 2));
        mx1 = fmaxf(mx1, __shfl_xor_sync(0xffffffffu, mx1, 1));
        mx1 = fmaxf(mx1, __shfl_xor_sync(0xffffffffu, mx1, 2));
        float nm0 = fmaxf(m0, mx0), nm1 = fmaxf(m1, mx1);
        float corr0 = __expf(m0 - nm0), corr1 = __expf(m1 - nm1);
        m0 = nm0; m1 = nm1;

        float rs0 = 0.f, rs1 = 0.f;
        uint32_t aP[4][4];
#pragma unroll
        for (int nt = 0; nt < 8; nt++) {
            float p0 = __expf(accS[nt][0] - m0);
            float p1 = __expf(accS[nt][1] - m0);
            float p2 = __expf(accS[nt][2] - m1);
            float p3 = __expf(accS[nt][3] - m1);
            rs0 += p0 + p1; rs1 += p2 + p3;
            const int i0 = (nt & 1) * 2;
            aP[nt >> 1][i0 + 0] = pkh(p0, p1);
            aP[nt >> 1][i0 + 1] = pkh(p2, p3);
        }
        rs0 += __shfl_xor_sync(0xffffffffu, rs0, 1);
        rs0 += __shfl_xor_sync(0xffffffffu, rs0, 2);
        rs1 += __shfl_xor_sync(0xffffffffu, rs1, 1);
        rs1 += __shfl_xor_sync(0xffffffffu, rs1, 2);
        l0 = l0 * corr0 + rs0;
        l1 = l1 * corr1 + rs1;

#pragma unroll
        for (int nt = 0; nt < 12; nt++) {
            accO[nt][0] *= corr0; accO[nt][1] *= corr0;
            accO[nt][2] *= corr1; accO[nt][3] *= corr1;
        }

        // ---- O += P V ----
#pragma unroll
        for (int kt2 = 0; kt2 < 4; kt2++) {
            const uint32_t toff = (uint32_t)(kt2 * 16 * 208);
            uint32_t a0 = aP[kt2][0], a1 = aP[kt2][1], a2 = aP[kt2][2], a3 = aP[kt2][3];
#pragma unroll
            for (int p = 0; p < 6; p++) {
                uint32_t v0, v1, v2, v3;
                ldm_x4_t(v0, v1, v2, v3, v_b + toff + (uint32_t)(p * 32));
                mma_f16(accO[2*p][0], accO[2*p][1], accO[2*p][2], accO[2*p][3],
                        a0, a1, a2, a3, v0, v1);
                mma_f16(accO[2*p+1][0], accO[2*p+1][1], accO[2*p+1][2], accO[2*p+1][3],
                        a0, a1, a2, a3, v2, v3);
            }
        }
        __syncthreads();
        if (kt + 2 < nkt) issue_tile(kt + 2, kt & 1);
    }

    // ---- epilogue: fp16 att ----
    const float inv0 = 1.f / l0;
    const float inv1 = 1.f / l1;
    const size_t grow0 = (size_t)(b * T_SEQ + qtp * 128 + r0l);
    const size_t grow1 = grow0 + 8;
#pragma unroll
    for (int nt = 0; nt < 12; nt++) {
        const int col = h * HD + nt * 8 + 2 * lc;
        *(uint32_t*)(atth + grow0 * C_EMB + col) = pkh(accO[nt][0] * inv0, accO[nt][1] * inv0);
        *(uint32_t*)(atth + grow1 * C_EMB + col) = pkh(accO[nt][2] * inv1, accO[nt][3] * inv1);
    }
}

// ---------------------------------------------------------------------------
// Launch
// ---------------------------------------------------------------------------
extern "C" void kernel_launch(void* const* d_in, const int* in_sizes, int n_in,
                              void* d_out, int out_size)
{
    (void)in_sizes; (void)n_in; (void)out_size;
    const float* x  = (const float*)d_in[0];
    const float* w1 = (const float*)d_in[1];
    const float* b1 = (const float*)d_in[2];
    const float* w2 = (const float*)d_in[3];
    const float* b2 = (const float*)d_in[4];
    float* out = (float*)d_out;

    __half *xh, *w1h, *w2h, *qh, *ah;
    cudaGetSymbolAddress((void**)&xh, g_xh);
    cudaGetSymbolAddress((void**)&w1h, g_w1h);
    cudaGetSymbolAddress((void**)&w2h, g_w2h);
    cudaGetSymbolAddress((void**)&qh, g_qkvh);
    cudaGetSymbolAddress((void**)&ah, g_atth);

    cudaFuncSetAttribute(gemm_f16<true>,
                         cudaFuncAttributeMaxDynamicSharedMemorySize, GEMM_SMEM_BYTES);
    cudaFuncSetAttribute(gemm_f16<false>,
                         cudaFuncAttributeMaxDynamicSharedMemorySize, GEMM_SMEM_BYTES);
    cudaFuncSetAttribute(flash_f16,
                         cudaFuncAttributeMaxDynamicSharedMemorySize, FL_SMEM_BYTES);

    // converts
    cvt_f16<<<256, 256>>>(x,  xh,  M_ROWS * C_EMB / 4);
    cvt_f16<<<256, 256>>>(w1, w1h, 3 * C_EMB * C_EMB / 4);
    cvt_f16<<<64,  256>>>(w2, w2h, C_EMB * C_EMB / 4);

    // QKV projection -> fp16 qkv
    gemm_f16<true><<<dim3(3 * C_EMB / 128, M_ROWS / 64), 128, GEMM_SMEM_BYTES>>>(
        xh, w1h, b1, nullptr, qh, 3 * C_EMB);

    // Causal attention -> fp16 att
    flash_f16<<<dim3(T_SEQ / 128, NH, BATCH), 256, FL_SMEM_BYTES>>>(qh, ah);

    // Output projection -> fp32 out
    gemm_f16<false><<<dim3(C_EMB / 128, M_ROWS / 64), 128, GEMM_SMEM_BYTES>>>(
        ah, w2h, b2, out, nullptr, C_EMB);
}